// round 7
// baseline (speedup 1.0000x reference)
#include <cuda_runtime.h>
#include <math.h>
#include <float.h>

#define Bn   4
#define Hn   32
#define HKV  8
#define Gn   4
#define Dn   128
#define Pn   128
#define Sn   64
#define KP   16
#define NEGV (-1000000000.0f)
#define SM_SCALE 0.08838834764831845f

typedef unsigned long long ull;

// Scratch (allocation-free rule: __device__ globals)
__device__ float g_qr    [Bn*Hn*Dn];      // roped q (unscaled)
__device__ float g_kr    [Bn*HKV*Dn];     // roped current k
__device__ float g_scores[Bn*Hn*Pn*Sn];   // 4 MB masked score matrix
__device__ float g_stats [Bn*Hn*Pn];      // per-page max
__device__ int   g_sel   [Bn*Hn*KP];
__device__ float g_cur   [Bn*Hn];         // current-token score
__device__ float g_max   [Bn*Hn];         // softmax max per head
__device__ float g_part  [Bn*Hn*KP*Dn];   // per-(head,page) partial sum(exp*V)
__device__ float g_pden  [Bn*Hn*KP];      // per-(head,page) partial denom
__device__ int   g_cnt   [Bn*Hn];         // arrival counters (zero-init)

__device__ __forceinline__ void rope_cs(int t, float pos, float& c, float& s) {
    float inv = 1.0f / powf(10000.0f, (float)t * (2.0f / (float)Dn));
    float ang = pos * inv;
    c = cosf(ang); s = sinf(ang);
}

// f32x2 packed math (SASS FFMA2/FADD2 — only reachable via PTX)
__device__ __forceinline__ ull fma2(ull a, ull b, ull c) {
    ull d;
    asm("fma.rn.f32x2 %0, %1, %2, %3;" : "=l"(d) : "l"(a), "l"(b), "l"(c));
    return d;
}
__device__ __forceinline__ ull add2(ull a, ull b) {
    ull d;
    asm("add.rn.f32x2 %0, %1, %2;" : "=l"(d) : "l"(a), "l"(b));
    return d;
}
__device__ __forceinline__ ull pack2(float lo, float hi) {
    ull d;
    asm("mov.b64 %0, {%1, %2};" : "=l"(d) : "f"(lo), "f"(hi));
    return d;
}
__device__ __forceinline__ void unpack2(ull v, float& lo, float& hi) {
    asm("mov.b64 {%0, %1}, %2;" : "=f"(lo), "=f"(hi) : "l"(v));
}

// ---------------------------------------------------------------- kernel 0
// RoPE (neox) for q (B*H heads) and current k (B*HKV heads). 64 threads/blk.
__global__ void prep_kernel(const float* __restrict__ q,
                            const float* __restrict__ k,
                            const int*   __restrict__ timestep)
{
    int i = blockIdx.x;          // 0..159
    int t = threadIdx.x;         // 0..63
    float pos = (float)(timestep[0] - 1);
    float c, s; rope_cs(t, pos, c, s);

    const float* src;
    float* dst;
    if (i < Bn*Hn) { src = q + (size_t)i*Dn;          dst = g_qr + (size_t)i*Dn; }
    else           { src = k + (size_t)(i-Bn*Hn)*Dn;  dst = g_kr + (size_t)(i-Bn*Hn)*Dn; }

    float x1 = src[t], x2 = src[t+64];
    dst[t]    = x1*c - x2*s;
    dst[t+64] = x1*s + x2*c;
}

// packed butterfly combine: element at +d kept by lanes with (lane & o)
__device__ __forceinline__ ull bcomb(ull a, ull b, int o, int lane) {
    ull send = (lane & o) ? a : b;
    ull recv = __shfl_xor_sync(0xffffffffu, send, o);
    ull keep = (lane & o) ? b : a;
    return add2(keep, recv);
}

// ---------------------------------------------------------------- kernel 1
// One block per (page, b*HKV): 256 threads, 8 warps x 8 tokens.
// Lane owns dims [4*lane, 4*lane+4); q pre-roped, packed across head pairs.
// Inner loop in f32x2 (FFMA2); mostly-packed butterfly transpose-reduce.
__global__ void __launch_bounds__(256, 4)
score_kernel(const int*   __restrict__ k_cache,
             const float* __restrict__ kv_scale,
             const int*   __restrict__ lengths)
{
    int p   = blockIdx.x;
    int bh  = blockIdx.y;            // b*HKV + hkv
    int b   = bh >> 3, hkv = bh & 7;
    int tid = threadIdx.x;
    int w   = tid >> 5, lane = tid & 31;
    int len = max(lengths[b], 1);
    int head0 = b*Hn + hkv*Gn;

    if (p*Sn >= len) {
        // fully masked page. Only page Pn-1 can ever be selected while masked.
        if (p == Pn-1 && tid < Sn) {
            #pragma unroll
            for (int g = 0; g < Gn; g++)
                g_scores[(size_t)(head0+g)*Pn*Sn + p*Sn + tid] = NEGV;
        }
        if (tid < Gn) g_stats[(head0+tid)*Pn + p] = NEGV;
        return;
    }

    // q: lane owns dims 4*lane..4*lane+3; packed across head pairs (g, g+1)
    ull qp[2][4];
    {
        float qa[Gn][4];
        #pragma unroll
        for (int g = 0; g < Gn; g++) {
            float4 t4 = *(const float4*)(g_qr + (size_t)(head0+g)*Dn + 4*lane);
            qa[g][0]=t4.x; qa[g][1]=t4.y; qa[g][2]=t4.z; qa[g][3]=t4.w;
        }
        #pragma unroll
        for (int i = 0; i < 4; i++) {
            qp[0][i] = pack2(qa[0][i], qa[1][i]);
            qp[1][i] = pack2(qa[2][i], qa[3][i]);
        }
    }

    float sks = kv_scale[0] * SM_SCALE;

    const int4* kbase = (const int4*)(k_cache +
        ((((size_t)b*Pn + p)*Sn + w*8)*HKV + hkv)*Dn) + lane;

    // final lane -> (g, t): g = 2*bit4 + bit1, t = 2*bit3 + bit2 (bit0 dup)
    int g  = 2*((lane >> 4) & 1) + ((lane >> 1) & 1);
    int tt = 2*((lane >> 3) & 1) + ((lane >> 2) & 1);

    float pmax = NEGV;
    #pragma unroll
    for (int c = 0; c < 2; c++) {
        int4 kv[4];
        #pragma unroll
        for (int t = 0; t < 4; t++)
            kv[t] = kbase[(size_t)(c*4 + t) * (HKV*Dn/4)];

        // vp[t*2 + gp]: halves = heads (2gp, 2gp+1)
        ull vp[8];
        #pragma unroll
        for (int i = 0; i < 8; i++) vp[i] = 0ull;

        #pragma unroll
        for (int t = 0; t < 4; t++) {
            float f[4] = {(float)kv[t].x, (float)kv[t].y,
                          (float)kv[t].z, (float)kv[t].w};
            #pragma unroll
            for (int i = 0; i < 4; i++) {
                ull fb = pack2(f[i], f[i]);
                vp[t*2+0] = fma2(fb, qp[0][i], vp[t*2+0]);
                vp[t*2+1] = fma2(fb, qp[1][i], vp[t*2+1]);
            }
        }

        // butterfly transpose-reduce (16 scalars over 32 lanes):
        // stage o=16: g-bit1 (packed pairs gp)
        ull r[4];
        #pragma unroll
        for (int t = 0; t < 4; t++)
            r[t] = bcomb(vp[t*2+0], vp[t*2+1], 16, lane);
        // stage o=8: t-bit1
        ull r2[2];
        r2[0] = bcomb(r[0], r[2], 8, lane);
        r2[1] = bcomb(r[1], r[3], 8, lane);
        // stage o=4: t-bit0
        ull r3 = bcomb(r2[0], r2[1], 4, lane);
        // stage o=2: g-bit0 (cross-half, scalar)
        float lo, hi; unpack2(r3, lo, hi);
        float send = (lane & 2) ? lo : hi;
        float recv = __shfl_xor_sync(0xffffffffu, send, 2);
        float v = ((lane & 2) ? hi : lo) + recv;
        // final fold over lane bit 0 (duplicated)
        v += __shfl_xor_sync(0xffffffffu, v, 1);

        int tok = w*8 + c*4 + tt;
        bool valid = p*Sn + tok < len;
        float sc = valid ? v*sks : NEGV;
        if (!(lane & 1))
            g_scores[(size_t)(head0+g)*Pn*Sn + p*Sn + tok] = sc;
        pmax = fmaxf(pmax, sc);
    }

    // per-g page max: reduce over t bits (lane bits 3,2); bits 1,0 homogeneous
    pmax = fmaxf(pmax, __shfl_xor_sync(0xffffffffu, pmax, 8));
    pmax = fmaxf(pmax, __shfl_xor_sync(0xffffffffu, pmax, 4));

    __shared__ float smax[8][Gn];
    if ((lane & 0b01101) == 0) smax[w][g] = pmax;   // lanes 0,2,16,18
    __syncthreads();
    if (tid < 32) {
        // tid = g2*8 + w2
        float v = smax[tid & 7][tid >> 3];
        #pragma unroll
        for (int o = 4; o >= 1; o >>= 1)
            v = fmaxf(v, __shfl_xor_sync(0xffffffffu, v, o));
        if ((tid & 7) == 0)
            g_stats[(head0 + (tid >> 3))*Pn + p] = v;
    }
}

// ---------------------------------------------------------------- kernel 2
// One WARP per head (4 heads/block, 32 blocks). Current score from pre-roped
// q/k; register-resident top-15 (jax.lax.top_k semantics) + forced page 127.
__device__ __forceinline__ unsigned int fkey(float f) {
    unsigned int u = __float_as_uint(f);
    return u ^ ((u & 0x80000000u) ? 0xFFFFFFFFu : 0x80000000u);
}

__global__ void topk_kernel(float* __restrict__ out_idx, int write_idx)
{
    int head = blockIdx.x * 4 + (threadIdx.x >> 5);
    int lane = threadIdx.x & 31;
    int b = head >> 5;
    int hkv = (head & (Hn-1)) >> 2;

    // current-token score from pre-roped vectors
    float4 qa = *(const float4*)(g_qr + (size_t)head*Dn + 4*lane);
    float4 ka = *(const float4*)(g_kr + (size_t)(b*HKV + hkv)*Dn + 4*lane);
    float prod = qa.x*ka.x + qa.y*ka.y + qa.z*ka.z + qa.w*ka.w;
    #pragma unroll
    for (int o = 16; o >= 1; o >>= 1)
        prod += __shfl_xor_sync(0xffffffffu, prod, o);
    float curv = prod * SM_SCALE;

    // register-resident top-15: lane owns indices lane, +32, +64, +96
    const float* st = g_stats + head*Pn;
    unsigned long long keys[4];
    #pragma unroll
    for (int j = 0; j < 4; j++) {
        int idx = lane + j*32;
        keys[j] = (idx < Pn-1)
            ? (((unsigned long long)fkey(st[idx]) << 32) | (unsigned int)(~idx))
            : 0ull;
    }

    int mysel = 0;
    int bidx0 = 0;
    #pragma unroll
    for (int it = 0; it < KP-1; it++) {
        unsigned long long best = keys[0];
        #pragma unroll
        for (int j = 1; j < 4; j++) best = (keys[j] > best) ? keys[j] : best;
        #pragma unroll
        for (int o = 16; o >= 1; o >>= 1) {
            unsigned long long u = __shfl_xor_sync(0xffffffffu, best, o);
            best = (u > best) ? u : best;
        }
        int bidx = (int)(~(unsigned int)(best & 0xFFFFFFFFull));
        if (lane == it) mysel = bidx;
        if (it == 0) bidx0 = bidx;
        #pragma unroll
        for (int j = 0; j < 4; j++) if (keys[j] == best) keys[j] = 0ull;
    }

    if (lane < KP-1) {
        g_sel[head*KP + lane] = mysel;
        if (write_idx) out_idx[head*KP + lane] = (float)mysel;
    }
    if (lane == KP-1) {
        g_sel[head*KP + lane] = Pn-1;
        if (write_idx) out_idx[head*KP + lane] = (float)(Pn-1);
    }
    if (lane == 0) {
        g_cur[head] = curv;
        float m = fmaxf(st[bidx0], st[Pn-1]);
        g_max[head] = fmaxf(m, curv);
    }
}

// ---------------------------------------------------------------- kernel 3
// One block per (head, selected page): 2048 blocks x 256 threads.
// 8 warps x 8 tokens each; partial exp-weighted V sums; last block per head
// finalizes (deterministic fixed-order sum).
__global__ void __launch_bounds__(256, 4)
attn_kernel(const int*   __restrict__ v_cache,
            const float* __restrict__ v_cur,
            const float* __restrict__ kv_scale,
            float* __restrict__ out)
{
    __shared__ float  w[Sn];
    __shared__ float4 part[8][32];
    __shared__ int    s_last;

    int bid  = blockIdx.x;
    int head = bid >> 4;
    int kp   = bid & (KP-1);
    int tid  = threadIdx.x;
    int warp = tid >> 5, lane = tid & 31;
    int b = head >> 5;
    int hkv = (head & (Hn-1)) >> 2;

    int page = g_sel[head*KP + kp];
    float m  = g_max[head];

    if (tid < Sn)
        w[tid] = expf(g_scores[(size_t)head*Pn*Sn + page*Sn + tid] - m);
    __syncthreads();

    if (warp == 0) {
        float s = w[lane] + w[lane + 32];
        #pragma unroll
        for (int o = 16; o >= 1; o >>= 1)
            s += __shfl_xor_sync(0xffffffffu, s, o);
        if (lane == 0) g_pden[head*KP + kp] = s;
    }

    // V accumulation: warp handles tokens s == warp (mod 8); batch 8 loads
    const int4* vp = (const int4*)(v_cache +
        (((size_t)(b*Pn + page)*Sn)*HKV + hkv)*Dn) + lane;
    int4 vv[8];
    #pragma unroll
    for (int s2 = 0; s2 < 8; s2++)
        vv[s2] = vp[(size_t)(s2*8 + warp) * (HKV*Dn/4)];

    float a0=0.f, a1=0.f, a2=0.f, a3=0.f;
    #pragma unroll
    for (int s2 = 0; s2 < 8; s2++) {
        float ww = w[s2*8 + warp];
        a0 += ww*(float)vv[s2].x; a1 += ww*(float)vv[s2].y;
        a2 += ww*(float)vv[s2].z; a3 += ww*(float)vv[s2].w;
    }
    part[warp][lane] = make_float4(a0, a1, a2, a3);
    __syncthreads();

    if (tid < Dn) {
        int lane2 = tid >> 2, comp = tid & 3;
        float acc = 0.f;
        #pragma unroll
        for (int g2 = 0; g2 < 8; g2++) {
            float4 pv = part[g2][lane2];
            acc += (comp==0) ? pv.x : (comp==1) ? pv.y : (comp==2) ? pv.z : pv.w;
        }
        g_part[((size_t)head*KP + kp)*Dn + tid] = acc;
    }

    // arrival counter: last block of this head finalizes (deterministic sum)
    __threadfence();
    __syncthreads();
    if (tid == 0) {
        int old = atomicAdd(&g_cnt[head], 1);
        s_last = (old == KP-1) ? 1 : 0;
        if (s_last) g_cnt[head] = 0;   // reset for next graph replay
    }
    __syncthreads();
    if (!s_last) return;
    __threadfence();

    if (tid < Dn) {
        float acc = 0.f;
        const float* pp = g_part + (size_t)head*KP*Dn + tid;
        #pragma unroll
        for (int j = 0; j < KP; j++) acc += pp[j*Dn];

        float ecur = expf(g_cur[head] - m);
        float den = ecur;
        const float* dp = g_pden + head*KP;
        #pragma unroll
        for (int j = 0; j < KP; j++) den += dp[j];

        float o = acc * kv_scale[1] + ecur * v_cur[(size_t)(b*HKV + hkv)*Dn + tid];
        out[(size_t)head*Dn + tid] = o / den;
    }
}

// ---------------------------------------------------------------- launch
extern "C" void kernel_launch(void* const* d_in, const int* in_sizes, int n_in,
                              void* d_out, int out_size)
{
    const float* q        = (const float*)d_in[0];
    const float* k        = (const float*)d_in[1];
    const float* v        = (const float*)d_in[2];
    const float* kv_scale = (const float*)d_in[3];
    const int*   k_cache  = (const int*)  d_in[4];
    const int*   v_cache  = (const int*)  d_in[5];
    const int*   lengths  = (const int*)  d_in[6];
    const int*   timestep = (const int*)  d_in[7];
    float* out = (float*)d_out;

    int write_idx = (out_size >= Bn*Hn*Dn + Bn*Hn*KP) ? 1 : 0;

    prep_kernel<<<Bn*Hn + Bn*HKV, 64>>>(q, k, timestep);
    score_kernel<<<dim3(Pn, Bn*HKV), 256>>>(k_cache, kv_scale, lengths);
    topk_kernel<<<Bn*Hn/4, 128>>>(out + Bn*Hn*Dn, write_idx);
    attn_kernel<<<Bn*Hn*KP, 256>>>(v_cache, v, kv_scale, out);
}

// round 8
// speedup vs baseline: 1.0500x; 1.0500x over previous
#include <cuda_runtime.h>
#include <math.h>
#include <float.h>

#define Bn   4
#define Hn   32
#define HKV  8
#define Gn   4
#define Dn   128
#define Pn   128
#define Sn   64
#define KP   16
#define NEGV (-1000000000.0f)
#define SM_SCALE 0.08838834764831845f

// Scratch (allocation-free rule: __device__ globals)
__device__ float g_qr    [Bn*Hn*Dn];      // roped q (unscaled)
__device__ float g_kr    [Bn*HKV*Dn];     // roped current k
__device__ float g_scores[Bn*Hn*Pn*Sn];   // 4 MB masked score matrix
__device__ float g_stats [Bn*Hn*Pn];      // per-page max
__device__ int   g_sel   [Bn*Hn*KP];
__device__ float g_cur   [Bn*Hn];         // current-token score
__device__ float g_max   [Bn*Hn];         // softmax max per head
__device__ float g_part  [Bn*Hn*KP*Dn];   // per-(head,page) partial sum(exp*V)
__device__ float g_pden  [Bn*Hn*KP];      // per-(head,page) partial denom

__device__ __forceinline__ void rope_cs(int t, float pos, float& c, float& s) {
    float inv = 1.0f / powf(10000.0f, (float)t * (2.0f / (float)Dn));
    float ang = pos * inv;
    c = cosf(ang); s = sinf(ang);
}

// ---------------------------------------------------------------- kernel 0
// RoPE (neox) for q (B*H heads) and current k (B*HKV heads). 64 threads/blk.
__global__ void prep_kernel(const float* __restrict__ q,
                            const float* __restrict__ k,
                            const int*   __restrict__ timestep)
{
    int i = blockIdx.x;          // 0..159
    int t = threadIdx.x;         // 0..63
    float pos = (float)(timestep[0] - 1);
    float c, s; rope_cs(t, pos, c, s);

    const float* src;
    float* dst;
    if (i < Bn*Hn) { src = q + (size_t)i*Dn;          dst = g_qr + (size_t)i*Dn; }
    else           { src = k + (size_t)(i-Bn*Hn)*Dn;  dst = g_kr + (size_t)(i-Bn*Hn)*Dn; }

    float x1 = src[t], x2 = src[t+64];
    dst[t]    = x1*c - x2*s;
    dst[t+64] = x1*s + x2*c;
}

// ---------------------------------------------------------------- kernel 1
// One block per (page, b*HKV): 256 threads, 8 warps x 8 tokens.
// Lane owns dims [4*lane, 4*lane+4); q pre-roped in registers.
// Two 4-token chunks; butterfly transpose-reduce of 16 vals over 32 lanes.
__global__ void __launch_bounds__(256, 4)
score_kernel(const int*   __restrict__ k_cache,
             const float* __restrict__ kv_scale,
             const int*   __restrict__ lengths)
{
    int p   = blockIdx.x;
    int bh  = blockIdx.y;            // b*HKV + hkv
    int b   = bh >> 3, hkv = bh & 7;
    int tid = threadIdx.x;
    int w   = tid >> 5, lane = tid & 31;
    int len = max(lengths[b], 1);
    int head0 = b*Hn + hkv*Gn;

    if (p*Sn >= len) {
        // fully masked page. Only page Pn-1 can ever be selected while masked.
        if (p == Pn-1 && tid < Sn) {
            #pragma unroll
            for (int g = 0; g < Gn; g++)
                g_scores[(size_t)(head0+g)*Pn*Sn + p*Sn + tid] = NEGV;
        }
        if (tid < Gn) g_stats[(head0+tid)*Pn + p] = NEGV;
        return;
    }

    // q: lane owns dims 4*lane..4*lane+3, all 4 heads (pre-roped, unscaled)
    float4 qr[Gn];
    #pragma unroll
    for (int g = 0; g < Gn; g++)
        qr[g] = *(const float4*)(g_qr + (size_t)(head0+g)*Dn + 4*lane);

    float sks = kv_scale[0] * SM_SCALE;

    const int4* kbase = (const int4*)(k_cache +
        ((((size_t)b*Pn + p)*Sn + w*8)*HKV + hkv)*Dn) + lane;

    // lane -> (g, t) after butterfly: g = (lane>>3)&3, t = (lane>>1)&3
    int g  = (lane >> 3) & 3;
    int tt = (lane >> 1) & 3;

    float pmax = NEGV;
    #pragma unroll
    for (int c = 0; c < 2; c++) {
        int4 kv[4];
        #pragma unroll
        for (int t = 0; t < 4; t++)
            kv[t] = kbase[(size_t)(c*4 + t) * (HKV*Dn/4)];

        float vals[16];
        #pragma unroll
        for (int i = 0; i < 16; i++) vals[i] = 0.f;

        #pragma unroll
        for (int t = 0; t < 4; t++) {
            float f0=(float)kv[t].x, f1=(float)kv[t].y,
                  f2=(float)kv[t].z, f3=(float)kv[t].w;
            #pragma unroll
            for (int gg = 0; gg < Gn; gg++)
                vals[gg*4+t] += f0*qr[gg].x + f1*qr[gg].y
                              + f2*qr[gg].z + f3*qr[gg].w;
        }

        // butterfly: stages (o=16,d=8) (8,4) (4,2) (2,1); then fold lane bit 0
        #pragma unroll
        for (int st = 0; st < 4; st++) {
            int o = 16 >> st, d = 8 >> st;
            #pragma unroll
            for (int a = 0; a < 8; a++) {
                if (a >= d) break;
                float lo = vals[a], hi = vals[a+d];
                float send = (lane & o) ? lo : hi;
                float recv = __shfl_xor_sync(0xffffffffu, send, o);
                vals[a] = ((lane & o) ? hi : lo) + recv;
            }
        }
        float v = vals[0] + __shfl_xor_sync(0xffffffffu, vals[0], 1);

        int tok = w*8 + c*4 + tt;
        bool valid = p*Sn + tok < len;
        float sc = valid ? v*sks : NEGV;
        if (!(lane & 1))
            g_scores[(size_t)(head0+g)*Pn*Sn + p*Sn + tok] = sc;
        pmax = fmaxf(pmax, sc);
    }

    // per-g page max: reduce over lane bits 4,2 (bit 1 already duplicated)
    pmax = fmaxf(pmax, __shfl_xor_sync(0xffffffffu, pmax, 4));
    pmax = fmaxf(pmax, __shfl_xor_sync(0xffffffffu, pmax, 2));

    __shared__ float smax[8][Gn];
    if ((lane & 7) == 0) smax[w][g] = pmax;
    __syncthreads();
    if (tid < 32) {
        // tid = g2*8 + w2
        float v = smax[tid & 7][tid >> 3];
        #pragma unroll
        for (int o = 4; o >= 1; o >>= 1)
            v = fmaxf(v, __shfl_xor_sync(0xffffffffu, v, o));
        if ((tid & 7) == 0)
            g_stats[(head0 + (tid >> 3))*Pn + p] = v;
    }
}

// ---------------------------------------------------------------- kernel 2
// One WARP per head (4 heads/block, 32 blocks). Current score from pre-roped
// q/k; register-resident top-15 (jax.lax.top_k semantics) + forced page 127.
__device__ __forceinline__ unsigned int fkey(float f) {
    unsigned int u = __float_as_uint(f);
    return u ^ ((u & 0x80000000u) ? 0xFFFFFFFFu : 0x80000000u);
}

__global__ void topk_kernel(float* __restrict__ out_idx, int write_idx)
{
    int head = blockIdx.x * 4 + (threadIdx.x >> 5);
    int lane = threadIdx.x & 31;
    int b = head >> 5;
    int hkv = (head & (Hn-1)) >> 2;

    // current-token score from pre-roped vectors
    float4 qa = *(const float4*)(g_qr + (size_t)head*Dn + 4*lane);
    float4 ka = *(const float4*)(g_kr + (size_t)(b*HKV + hkv)*Dn + 4*lane);
    float prod = qa.x*ka.x + qa.y*ka.y + qa.z*ka.z + qa.w*ka.w;
    #pragma unroll
    for (int o = 16; o >= 1; o >>= 1)
        prod += __shfl_xor_sync(0xffffffffu, prod, o);
    float curv = prod * SM_SCALE;

    // register-resident top-15: lane owns indices lane, +32, +64, +96
    const float* st = g_stats + head*Pn;
    unsigned long long keys[4];
    #pragma unroll
    for (int j = 0; j < 4; j++) {
        int idx = lane + j*32;
        keys[j] = (idx < Pn-1)
            ? (((unsigned long long)fkey(st[idx]) << 32) | (unsigned int)(~idx))
            : 0ull;
    }

    int mysel = 0;
    int bidx0 = 0;
    #pragma unroll
    for (int it = 0; it < KP-1; it++) {
        unsigned long long best = keys[0];
        #pragma unroll
        for (int j = 1; j < 4; j++) best = (keys[j] > best) ? keys[j] : best;
        #pragma unroll
        for (int o = 16; o >= 1; o >>= 1) {
            unsigned long long u = __shfl_xor_sync(0xffffffffu, best, o);
            best = (u > best) ? u : best;
        }
        int bidx = (int)(~(unsigned int)(best & 0xFFFFFFFFull));
        if (lane == it) mysel = bidx;
        if (it == 0) bidx0 = bidx;
        #pragma unroll
        for (int j = 0; j < 4; j++) if (keys[j] == best) keys[j] = 0ull;
    }

    if (lane < KP-1) {
        g_sel[head*KP + lane] = mysel;
        if (write_idx) out_idx[head*KP + lane] = (float)mysel;
    }
    if (lane == KP-1) {
        g_sel[head*KP + lane] = Pn-1;
        if (write_idx) out_idx[head*KP + lane] = (float)(Pn-1);
    }
    if (lane == 0) {
        g_cur[head] = curv;
        float m = fmaxf(st[bidx0], st[Pn-1]);
        g_max[head] = fmaxf(m, curv);
    }
}

// ---------------------------------------------------------------- kernel 3
// One block per (head, selected page): 2048 blocks x 128 threads.
// Computes partial sum(exp(score-m) * V) over 64 tokens + partial denom.
// (R2 configuration — measured fastest: no explicit batching, no bounds.)
__global__ void attn_part_kernel(const int* __restrict__ v_cache)
{
    __shared__ float  w[Sn];
    __shared__ float4 part[4][32];

    int bid  = blockIdx.x;
    int head = bid >> 4;
    int kp   = bid & (KP-1);
    int tid  = threadIdx.x;
    int warp = tid >> 5, lane = tid & 31;
    int b = head >> 5;                 // head / Hn
    int hkv = (head & (Hn-1)) >> 2;    // (head % Hn) / Gn

    int page = g_sel[head*KP + kp];
    float m  = g_max[head];

    if (tid < Sn)
        w[tid] = expf(g_scores[(size_t)head*Pn*Sn + page*Sn + tid] - m);
    __syncthreads();

    // partial denom (warp 0)
    if (warp == 0) {
        float s = w[lane] + w[lane + 32];
        #pragma unroll
        for (int o = 16; o >= 1; o >>= 1)
            s += __shfl_xor_sync(0xffffffffu, s, o);
        if (lane == 0) g_pden[head*KP + kp] = s;
    }

    // V accumulation: warp g handles tokens s == g (mod 4); lane -> 4 dims
    const int4* vp = (const int4*)(v_cache +
        (((size_t)(b*Pn + page)*Sn)*HKV + hkv)*Dn) + lane;
    float a0=0.f, a1=0.f, a2=0.f, a3=0.f;
    #pragma unroll
    for (int s2 = 0; s2 < Sn/4; s2++) {
        int srow = s2*4 + warp;
        int4 vv = vp[(size_t)srow * (HKV*Dn/4)];
        float ww = w[srow];
        a0 += ww*(float)vv.x; a1 += ww*(float)vv.y;
        a2 += ww*(float)vv.z; a3 += ww*(float)vv.w;
    }
    part[warp][lane] = make_float4(a0, a1, a2, a3);
    __syncthreads();

    int lane2 = tid >> 2, comp = tid & 3;
    float acc = 0.f;
    #pragma unroll
    for (int g2 = 0; g2 < 4; g2++) {
        float4 pv = part[g2][lane2];
        acc += (comp==0) ? pv.x : (comp==1) ? pv.y : (comp==2) ? pv.z : pv.w;
    }
    g_part[((size_t)head*KP + kp)*Dn + tid] = acc;
}

// ---------------------------------------------------------------- kernel 4
// Per head: sum 16 partials, add current token, normalize. 128 blocks x 128.
__global__ void attn_reduce_kernel(const float* __restrict__ v_cur,
                                   const float* __restrict__ kv_scale,
                                   float* __restrict__ out)
{
    int head = blockIdx.x;
    int tid  = threadIdx.x;
    int b = head >> 5;
    int hkv = (head & (Hn-1)) >> 2;

    float acc = 0.f;
    const float* pp = g_part + (size_t)head*KP*Dn + tid;
    #pragma unroll
    for (int kp = 0; kp < KP; kp++)
        acc += pp[kp*Dn];

    float m    = g_max[head];
    float ecur = expf(g_cur[head] - m);

    float den = ecur;
    const float* dp = g_pden + head*KP;
    #pragma unroll
    for (int kp = 0; kp < KP; kp++)
        den += dp[kp];

    float o = acc * kv_scale[1] + ecur * v_cur[(size_t)(b*HKV + hkv)*Dn + tid];
    out[(size_t)head*Dn + tid] = o / den;
}

// ---------------------------------------------------------------- launch
extern "C" void kernel_launch(void* const* d_in, const int* in_sizes, int n_in,
                              void* d_out, int out_size)
{
    const float* q        = (const float*)d_in[0];
    const float* k        = (const float*)d_in[1];
    const float* v        = (const float*)d_in[2];
    const float* kv_scale = (const float*)d_in[3];
    const int*   k_cache  = (const int*)  d_in[4];
    const int*   v_cache  = (const int*)  d_in[5];
    const int*   lengths  = (const int*)  d_in[6];
    const int*   timestep = (const int*)  d_in[7];
    float* out = (float*)d_out;

    int write_idx = (out_size >= Bn*Hn*Dn + Bn*Hn*KP) ? 1 : 0;

    prep_kernel<<<Bn*Hn + Bn*HKV, 64>>>(q, k, timestep);
    score_kernel<<<dim3(Pn, Bn*HKV), 256>>>(k_cache, kv_scale, lengths);
    topk_kernel<<<Bn*Hn/4, 128>>>(out + Bn*Hn*Dn, write_idx);
    attn_part_kernel<<<Bn*Hn*KP, 128>>>(v_cache);
    attn_reduce_kernel<<<Bn*Hn, 128>>>(v, kv_scale, out);
}

// round 9
// speedup vs baseline: 1.0868x; 1.0350x over previous
#include <cuda_runtime.h>
#include <math.h>
#include <float.h>

#define Bn   4
#define Hn   32
#define HKV  8
#define Gn   4
#define Dn   128
#define Pn   128
#define Sn   64
#define KP   16
#define NEGV (-1000000000.0f)
#define SM_SCALE 0.08838834764831845f

// Scratch (allocation-free rule: __device__ globals)
__device__ float g_qr    [Bn*Hn*Dn];      // roped q (unscaled)
__device__ float g_kr    [Bn*HKV*Dn];     // roped current k
__device__ float g_scores[Bn*Hn*Pn*Sn];   // 4 MB masked score matrix
__device__ float g_stats [Bn*Hn*Pn];      // per-page max
__device__ float g_part  [Bn*Hn*KP*Dn];   // per-(head,page) partial sum(exp*V)
__device__ float g_pden  [Bn*Hn*KP];      // per-(head,page) partial denom
__device__ int   g_cnt   [Bn*Hn];         // arrival counters (zero-init)

__device__ __forceinline__ void rope_cs(int t, float pos, float& c, float& s) {
    float inv = 1.0f / powf(10000.0f, (float)t * (2.0f / (float)Dn));
    float ang = pos * inv;
    c = cosf(ang); s = sinf(ang);
}

// ---------------------------------------------------------------- kernel 0
// RoPE (neox) for q (B*H heads) and current k (B*HKV heads). 64 threads/blk.
__global__ void prep_kernel(const float* __restrict__ q,
                            const float* __restrict__ k,
                            const int*   __restrict__ timestep)
{
    int i = blockIdx.x;          // 0..159
    int t = threadIdx.x;         // 0..63
    float pos = (float)(timestep[0] - 1);
    float c, s; rope_cs(t, pos, c, s);

    const float* src;
    float* dst;
    if (i < Bn*Hn) { src = q + (size_t)i*Dn;          dst = g_qr + (size_t)i*Dn; }
    else           { src = k + (size_t)(i-Bn*Hn)*Dn;  dst = g_kr + (size_t)(i-Bn*Hn)*Dn; }

    float x1 = src[t], x2 = src[t+64];
    dst[t]    = x1*c - x2*s;
    dst[t+64] = x1*s + x2*c;
}

// ---------------------------------------------------------------- kernel 1
// One block per (page, b*HKV): 256 threads, 8 warps x 8 tokens.
// Lane owns dims [4*lane, 4*lane+4); q pre-roped in registers.
// Two 4-token chunks; butterfly transpose-reduce of 16 vals over 32 lanes.
__global__ void __launch_bounds__(256, 4)
score_kernel(const int*   __restrict__ k_cache,
             const float* __restrict__ kv_scale,
             const int*   __restrict__ lengths)
{
    int p   = blockIdx.x;
    int bh  = blockIdx.y;            // b*HKV + hkv
    int b   = bh >> 3, hkv = bh & 7;
    int tid = threadIdx.x;
    int w   = tid >> 5, lane = tid & 31;
    int len = max(lengths[b], 1);
    int head0 = b*Hn + hkv*Gn;

    if (p*Sn >= len) {
        // fully masked page. Only page Pn-1 can ever be selected while masked.
        if (p == Pn-1 && tid < Sn) {
            #pragma unroll
            for (int g = 0; g < Gn; g++)
                g_scores[(size_t)(head0+g)*Pn*Sn + p*Sn + tid] = NEGV;
        }
        if (tid < Gn) g_stats[(head0+tid)*Pn + p] = NEGV;
        return;
    }

    // q: lane owns dims 4*lane..4*lane+3, all 4 heads (pre-roped, unscaled)
    float4 qr[Gn];
    #pragma unroll
    for (int g = 0; g < Gn; g++)
        qr[g] = *(const float4*)(g_qr + (size_t)(head0+g)*Dn + 4*lane);

    float sks = kv_scale[0] * SM_SCALE;

    const int4* kbase = (const int4*)(k_cache +
        ((((size_t)b*Pn + p)*Sn + w*8)*HKV + hkv)*Dn) + lane;

    // lane -> (g, t) after butterfly: g = (lane>>3)&3, t = (lane>>1)&3
    int g  = (lane >> 3) & 3;
    int tt = (lane >> 1) & 3;

    float pmax = NEGV;
    #pragma unroll
    for (int c = 0; c < 2; c++) {
        int4 kv[4];
        #pragma unroll
        for (int t = 0; t < 4; t++)
            kv[t] = kbase[(size_t)(c*4 + t) * (HKV*Dn/4)];

        float vals[16];
        #pragma unroll
        for (int i = 0; i < 16; i++) vals[i] = 0.f;

        #pragma unroll
        for (int t = 0; t < 4; t++) {
            float f0=(float)kv[t].x, f1=(float)kv[t].y,
                  f2=(float)kv[t].z, f3=(float)kv[t].w;
            #pragma unroll
            for (int gg = 0; gg < Gn; gg++)
                vals[gg*4+t] += f0*qr[gg].x + f1*qr[gg].y
                              + f2*qr[gg].z + f3*qr[gg].w;
        }

        // butterfly: stages (o=16,d=8) (8,4) (4,2) (2,1); then fold lane bit 0
        #pragma unroll
        for (int st = 0; st < 4; st++) {
            int o = 16 >> st, d = 8 >> st;
            #pragma unroll
            for (int a = 0; a < 8; a++) {
                if (a >= d) break;
                float lo = vals[a], hi = vals[a+d];
                float send = (lane & o) ? lo : hi;
                float recv = __shfl_xor_sync(0xffffffffu, send, o);
                vals[a] = ((lane & o) ? hi : lo) + recv;
            }
        }
        float v = vals[0] + __shfl_xor_sync(0xffffffffu, vals[0], 1);

        int tok = w*8 + c*4 + tt;
        bool valid = p*Sn + tok < len;
        float sc = valid ? v*sks : NEGV;
        if (!(lane & 1))
            g_scores[(size_t)(head0+g)*Pn*Sn + p*Sn + tok] = sc;
        pmax = fmaxf(pmax, sc);
    }

    // per-g page max: reduce over lane bits 4,2 (bit 1 already duplicated)
    pmax = fmaxf(pmax, __shfl_xor_sync(0xffffffffu, pmax, 4));
    pmax = fmaxf(pmax, __shfl_xor_sync(0xffffffffu, pmax, 2));

    __shared__ float smax[8][Gn];
    if ((lane & 7) == 0) smax[w][g] = pmax;
    __syncthreads();
    if (tid < 32) {
        // tid = g2*8 + w2
        float v = smax[tid & 7][tid >> 3];
        #pragma unroll
        for (int o = 4; o >= 1; o >>= 1)
            v = fmaxf(v, __shfl_xor_sync(0xffffffffu, v, o));
        if ((tid & 7) == 0)
            g_stats[(head0 + (tid >> 3))*Pn + p] = v;
    }
}

// ---------------------------------------------------------------- kernel 2
// One block per (head, kp): 2048 blocks x 128 threads.
// Warp 0 re-derives the kp-th top page (jax.lax.top_k semantics), the
// current-token score and softmax max; then exp-weighted V partial sum.
// Last-arriving block per head finalizes (deterministic fixed-order sum).
__device__ __forceinline__ unsigned int fkey(float f) {
    unsigned int u = __float_as_uint(f);
    return u ^ ((u & 0x80000000u) ? 0xFFFFFFFFu : 0x80000000u);
}

__global__ void attn_kernel(const int*   __restrict__ v_cache,
                            const float* __restrict__ v_cur,
                            const float* __restrict__ kv_scale,
                            float* __restrict__ out,
                            float* __restrict__ out_idx, int write_idx)
{
    __shared__ float  w[Sn];
    __shared__ float4 part[4][32];
    __shared__ float  s_m, s_cur;
    __shared__ int    s_page, s_last;

    int bid  = blockIdx.x;
    int head = bid >> 4;
    int kp   = bid & (KP-1);
    int tid  = threadIdx.x;
    int warp = tid >> 5, lane = tid & 31;
    int b = head >> 5;                 // head / Hn
    int hkv = (head & (Hn-1)) >> 2;    // (head % Hn) / Gn

    const float* st = g_stats + head*Pn;

    if (warp == 0) {
        // current-token score from pre-roped q/k
        float4 qa = *(const float4*)(g_qr + (size_t)head*Dn + 4*lane);
        float4 ka = *(const float4*)(g_kr + (size_t)(b*HKV + hkv)*Dn + 4*lane);
        float prod = qa.x*ka.x + qa.y*ka.y + qa.z*ka.z + qa.w*ka.w;
        #pragma unroll
        for (int o = 16; o >= 1; o >>= 1)
            prod += __shfl_xor_sync(0xffffffffu, prod, o);
        float curv = prod * SM_SCALE;

        // top-k: iterate to rank kp (or rank 0 only, for forced page 127)
        unsigned long long keys[4];
        #pragma unroll
        for (int j = 0; j < 4; j++) {
            int idx = lane + j*32;
            keys[j] = (idx < Pn-1)
                ? (((unsigned long long)fkey(st[idx]) << 32) | (unsigned int)(~idx))
                : 0ull;
        }

        int iters = (kp == KP-1) ? 1 : (kp + 1);
        int bidx = 0, bidx0 = 0;
        for (int it = 0; it < iters; it++) {
            unsigned long long best = keys[0];
            #pragma unroll
            for (int j = 1; j < 4; j++) best = (keys[j] > best) ? keys[j] : best;
            #pragma unroll
            for (int o = 16; o >= 1; o >>= 1) {
                unsigned long long u = __shfl_xor_sync(0xffffffffu, best, o);
                best = (u > best) ? u : best;
            }
            bidx = (int)(~(unsigned int)(best & 0xFFFFFFFFull));
            if (it == 0) bidx0 = bidx;
            #pragma unroll
            for (int j = 0; j < 4; j++) if (keys[j] == best) keys[j] = 0ull;
        }
        int page = (kp == KP-1) ? (Pn-1) : bidx;
        float m = fmaxf(fmaxf(st[bidx0], st[Pn-1]), curv);

        if (lane == 0) {
            s_page = page; s_m = m; s_cur = curv;
            if (write_idx) out_idx[head*KP + kp] = (float)page;
        }
    }
    __syncthreads();

    int page = s_page;
    float m  = s_m;

    if (tid < Sn)
        w[tid] = expf(g_scores[(size_t)head*Pn*Sn + page*Sn + tid] - m);
    __syncthreads();

    // partial denom (warp 0)
    if (warp == 0) {
        float s = w[lane] + w[lane + 32];
        #pragma unroll
        for (int o = 16; o >= 1; o >>= 1)
            s += __shfl_xor_sync(0xffffffffu, s, o);
        if (lane == 0) g_pden[head*KP + kp] = s;
    }

    // V accumulation: warp g handles tokens s == g (mod 4); lane -> 4 dims
    const int4* vp = (const int4*)(v_cache +
        (((size_t)(b*Pn + page)*Sn)*HKV + hkv)*Dn) + lane;
    float a0=0.f, a1=0.f, a2=0.f, a3=0.f;
    #pragma unroll
    for (int s2 = 0; s2 < Sn/4; s2++) {
        int srow = s2*4 + warp;
        int4 vv = vp[(size_t)srow * (HKV*Dn/4)];
        float ww = w[srow];
        a0 += ww*(float)vv.x; a1 += ww*(float)vv.y;
        a2 += ww*(float)vv.z; a3 += ww*(float)vv.w;
    }
    part[warp][lane] = make_float4(a0, a1, a2, a3);
    __syncthreads();

    {
        int lane2 = tid >> 2, comp = tid & 3;
        float acc = 0.f;
        #pragma unroll
        for (int g2 = 0; g2 < 4; g2++) {
            float4 pv = part[g2][lane2];
            acc += (comp==0) ? pv.x : (comp==1) ? pv.y : (comp==2) ? pv.z : pv.w;
        }
        g_part[((size_t)head*KP + kp)*Dn + tid] = acc;
    }

    // arrival counter: last block of this head finalizes (deterministic sum)
    __threadfence();
    __syncthreads();
    if (tid == 0) {
        int old = atomicAdd(&g_cnt[head], 1);
        s_last = (old == KP-1) ? 1 : 0;
        if (s_last) g_cnt[head] = 0;   // reset for next graph replay
    }
    __syncthreads();
    if (!s_last) return;
    __threadfence();

    float acc = 0.f;
    const float* pp = g_part + (size_t)head*KP*Dn + tid;
    #pragma unroll
    for (int j = 0; j < KP; j++) acc += pp[j*Dn];

    float ecur = expf(s_cur - m);
    float den = ecur;
    const float* dp = g_pden + head*KP;
    #pragma unroll
    for (int j = 0; j < KP; j++) den += dp[j];

    float o = acc * kv_scale[1] + ecur * v_cur[(size_t)(b*HKV + hkv)*Dn + tid];
    out[(size_t)head*Dn + tid] = o / den;
}

// ---------------------------------------------------------------- launch
extern "C" void kernel_launch(void* const* d_in, const int* in_sizes, int n_in,
                              void* d_out, int out_size)
{
    const float* q        = (const float*)d_in[0];
    const float* k        = (const float*)d_in[1];
    const float* v        = (const float*)d_in[2];
    const float* kv_scale = (const float*)d_in[3];
    const int*   k_cache  = (const int*)  d_in[4];
    const int*   v_cache  = (const int*)  d_in[5];
    const int*   lengths  = (const int*)  d_in[6];
    const int*   timestep = (const int*)  d_in[7];
    float* out = (float*)d_out;

    int write_idx = (out_size >= Bn*Hn*Dn + Bn*Hn*KP) ? 1 : 0;

    prep_kernel<<<Bn*Hn + Bn*HKV, 64>>>(q, k, timestep);
    score_kernel<<<dim3(Pn, Bn*HKV), 256>>>(k_cache, kv_scale, lengths);
    attn_kernel<<<Bn*Hn*KP, 128>>>(v_cache, v, kv_scale, out,
                                   out + Bn*Hn*Dn, write_idx);
}